// round 1
// baseline (speedup 1.0000x reference)
#include <cuda_runtime.h>
#include <cuda_bf16.h>

#define B_  2
#define N_  1024
#define M_  1024
#define H_  128
#define SCALE_ (1.0f / 6.964404506368992f)  // 128^0.4 = 6.96440450636899...

// softmax weights scratch: s[b][m]
__device__ float g_s[B_ * M_];

__global__ __launch_bounds__(1024) void k_softmax(const float* __restrict__ keys,
                                                  const float* __restrict__ W,
                                                  const float* __restrict__ bias) {
    const int b = blockIdx.x;
    const int tid = threadIdx.x;

    __shared__ float sh_wcol[H_];
    __shared__ float sh_bsum;
    __shared__ float red[32];
    __shared__ float red2[32];

    // colsum(W): W is [H,H] row-major, wcol[h] = sum_o W[o,h]
    if (tid < H_) {
        float acc = 0.f;
        #pragma unroll 4
        for (int o = 0; o < H_; ++o) acc += W[o * H_ + tid];
        sh_wcol[tid] = acc;
    }
    if (tid == 0) {
        float bs = 0.f;
        #pragma unroll 4
        for (int i = 0; i < H_; ++i) bs += bias[i];
        sh_bsum = bs;
    }
    __syncthreads();

    // ks[b, tid] = dot(keys[b,tid,:], wcol) + bsum
    const float4* krow = reinterpret_cast<const float4*>(keys + ((size_t)b * M_ + tid) * H_);
    const float4* wc = reinterpret_cast<const float4*>(sh_wcol);
    float acc = 0.f;
    #pragma unroll
    for (int i = 0; i < H_ / 4; ++i) {
        float4 k4 = krow[i];
        float4 w4 = wc[i];
        acc = fmaf(k4.x, w4.x, acc);
        acc = fmaf(k4.y, w4.y, acc);
        acc = fmaf(k4.z, w4.z, acc);
        acc = fmaf(k4.w, w4.w, acc);
    }
    float x = SCALE_ * (acc + sh_bsum);

    // block max over 1024 values
    float m = x;
    #pragma unroll
    for (int o = 16; o > 0; o >>= 1) m = fmaxf(m, __shfl_xor_sync(0xffffffffu, m, o));
    if ((tid & 31) == 0) red[tid >> 5] = m;
    __syncthreads();
    if (tid < 32) {
        float v = red[tid];
        #pragma unroll
        for (int o = 16; o > 0; o >>= 1) v = fmaxf(v, __shfl_xor_sync(0xffffffffu, v, o));
        red[tid] = v;
    }
    __syncthreads();
    const float gmax = red[0];

    const float e = expf(x - gmax);

    // block sum
    float s = e;
    #pragma unroll
    for (int o = 16; o > 0; o >>= 1) s += __shfl_xor_sync(0xffffffffu, s, o);
    if ((tid & 31) == 0) red2[tid >> 5] = s;
    __syncthreads();
    if (tid < 32) {
        float v = red2[tid];
        #pragma unroll
        for (int o = 16; o > 0; o >>= 1) v += __shfl_xor_sync(0xffffffffu, v, o);
        red2[tid] = v;
    }
    __syncthreads();
    const float gsum = red2[0];

    g_s[b * M_ + tid] = e / gsum;
}

// out[b,n,m] = s[b,m] * values[b,n]; flat float4 grid-stride
__global__ __launch_bounds__(256) void k_out(const float* __restrict__ values,
                                             float* __restrict__ out) {
    const int total4 = B_ * N_ * M_ / 4;                  // 524288
    int idx = blockIdx.x * blockDim.x + threadIdx.x;
    const int stride = gridDim.x * blockDim.x;
    float4* o4 = reinterpret_cast<float4*>(out);
    const float4* s4 = reinterpret_cast<const float4*>(g_s);
    for (; idx < total4; idx += stride) {
        const int b = idx >> 18;                          // (N*M/4) = 262144 = 2^18
        const int r = idx & 262143;
        const int n = r >> 8;                             // M/4 = 256
        const int m4 = r & 255;
        const float v = values[b * N_ + n];
        float4 s = s4[(b << 8) + m4];
        o4[idx] = make_float4(s.x * v, s.y * v, s.z * v, s.w * v);
    }
}

extern "C" void kernel_launch(void* const* d_in, const int* in_sizes, int n_in,
                              void* d_out, int out_size) {
    // metadata order: queries, keys, values, W, b
    const float* keys   = (const float*)d_in[1];
    const float* values = (const float*)d_in[2];
    const float* W      = (const float*)d_in[3];
    const float* bias   = (const float*)d_in[4];
    float* out = (float*)d_out;

    k_softmax<<<B_, 1024>>>(keys, W, bias);
    k_out<<<2048, 256>>>(values, out);
}

// round 2
// speedup vs baseline: 1.2164x; 1.2164x over previous
#include <cuda_runtime.h>
#include <cuda_bf16.h>

#define B_  2
#define N_  1024
#define M_  1024
#define H_  128
#define SCALE_ (1.0f / 6.964404506368992f)  // 1 / 128^0.4

// softmax weights scratch: s[b][m]
__device__ float g_s[B_ * M_];

__global__ __launch_bounds__(1024) void k_softmax(const float* __restrict__ keys,
                                                  const float* __restrict__ W,
                                                  const float* __restrict__ bias) {
    const int b = blockIdx.x;
    const int tid = threadIdx.x;
    const int lane = tid & 31;
    const int warp = tid >> 5;

    __shared__ float sh_part[8][H_];   // partial column sums
    __shared__ float sh_wcol[H_];
    __shared__ float sh_bsum;
    __shared__ float red[32];
    __shared__ float red2[32];

    // ---- parallel colsum(W): wcol[c] = sum_o W[o][c] ----
    // 1024 threads: col c = tid&127, row-group g = tid>>7 (16 rows each).
    {
        const int c = tid & (H_ - 1);
        const int g = tid >> 7;
        const float* wp = W + (g * 16) * H_ + c;
        float a0 = 0.f, a1 = 0.f, a2 = 0.f, a3 = 0.f;
        #pragma unroll
        for (int r = 0; r < 16; r += 4) {
            a0 += wp[(r + 0) * H_];
            a1 += wp[(r + 1) * H_];
            a2 += wp[(r + 2) * H_];
            a3 += wp[(r + 3) * H_];
        }
        sh_part[g][c] = (a0 + a1) + (a2 + a3);
    }

    // ---- parallel bias sum (warp 0) ----
    if (warp == 0) {
        float bs = bias[lane] + bias[lane + 32] + bias[lane + 64] + bias[lane + 96];
        #pragma unroll
        for (int o = 16; o > 0; o >>= 1) bs += __shfl_xor_sync(0xffffffffu, bs, o);
        if (lane == 0) sh_bsum = bs;
    }
    __syncthreads();

    if (tid < H_) {
        float s = 0.f;
        #pragma unroll
        for (int g = 0; g < 8; ++g) s += sh_part[g][tid];
        sh_wcol[tid] = s;
    }
    __syncthreads();

    // ---- ks[b, tid] = dot(keys[b,tid,:], wcol) + bsum ----
    const float4* krow = reinterpret_cast<const float4*>(keys + ((size_t)b * M_ + tid) * H_);
    const float4* wc = reinterpret_cast<const float4*>(sh_wcol);
    float acc = 0.f;
    #pragma unroll
    for (int i = 0; i < H_ / 4; ++i) {
        float4 k4 = krow[i];
        float4 w4 = wc[i];
        acc = fmaf(k4.x, w4.x, acc);
        acc = fmaf(k4.y, w4.y, acc);
        acc = fmaf(k4.z, w4.z, acc);
        acc = fmaf(k4.w, w4.w, acc);
    }
    float x = SCALE_ * (acc + sh_bsum);

    // ---- block max ----
    float m = x;
    #pragma unroll
    for (int o = 16; o > 0; o >>= 1) m = fmaxf(m, __shfl_xor_sync(0xffffffffu, m, o));
    if (lane == 0) red[warp] = m;
    __syncthreads();
    if (tid < 32) {
        float v = red[tid];
        #pragma unroll
        for (int o = 16; o > 0; o >>= 1) v = fmaxf(v, __shfl_xor_sync(0xffffffffu, v, o));
        red[tid] = v;
    }
    __syncthreads();
    const float gmax = red[0];

    const float e = __expf(x - gmax);

    // ---- block sum ----
    float s = e;
    #pragma unroll
    for (int o = 16; o > 0; o >>= 1) s += __shfl_xor_sync(0xffffffffu, s, o);
    if (lane == 0) red2[warp] = s;
    __syncthreads();
    if (tid < 32) {
        float v = red2[tid];
        #pragma unroll
        for (int o = 16; o > 0; o >>= 1) v += __shfl_xor_sync(0xffffffffu, v, o);
        red2[tid] = v;
    }
    __syncthreads();
    const float gsum = red2[0];

    g_s[b * M_ + tid] = e / gsum;
}

// out[b,n,m] = s[b,m] * values[b,n]
// Each block owns 8 rows (same batch); s row held in registers, reused 8x.
__global__ __launch_bounds__(256) void k_out(const float* __restrict__ values,
                                             float* __restrict__ out) {
    const int tid = threadIdx.x;
    const int row0 = blockIdx.x * 8;               // 256 blocks * 8 = 2048 rows
    const int b = row0 >> 10;                      // N_=1024 rows per batch

    const float4* s4 = reinterpret_cast<const float4*>(g_s);
    float4* o4 = reinterpret_cast<float4*>(out);

    const float4 s = s4[(b << 8) + tid];           // M_/4 = 256 float4 per row

    #pragma unroll
    for (int r = 0; r < 8; ++r) {
        const int row = row0 + r;
        const float v = values[row];               // values flat [B*N]
        o4[(size_t)row * 256 + tid] =
            make_float4(s.x * v, s.y * v, s.z * v, s.w * v);
    }
}

extern "C" void kernel_launch(void* const* d_in, const int* in_sizes, int n_in,
                              void* d_out, int out_size) {
    // metadata order: queries, keys, values, W, b
    const float* keys   = (const float*)d_in[1];
    const float* values = (const float*)d_in[2];
    const float* W      = (const float*)d_in[3];
    const float* bias   = (const float*)d_in[4];
    float* out = (float*)d_out;

    k_softmax<<<B_, 1024>>>(keys, W, bias);
    k_out<<<256, 256>>>(values, out);
}

// round 3
// speedup vs baseline: 3.0233x; 2.4855x over previous
#include <cuda_runtime.h>
#include <cuda_bf16.h>

#define B_  2
#define N_  1024
#define M_  1024
#define H_  128
#define SCALE_ (1.0f / 6.964404506368992f)  // 1 / 128^0.4

__device__ float g_ks[B_ * M_];   // scaled logits (per-key part)
__device__ float g_s[B_ * M_];    // softmax weights

// ---------------------------------------------------------------------------
// K1: ks[r] = SCALE * (dot(keys[r,:], colsum(W)) + sum(b))
// grid 64 x 1024 threads; each block: redundant wcol compute (L2-hit after
// first wave) + 32 rows, one warp per row.
// ---------------------------------------------------------------------------
__global__ __launch_bounds__(1024) void k_ks(const float* __restrict__ keys,
                                             const float* __restrict__ W,
                                             const float* __restrict__ bias) {
    const int tid = threadIdx.x;
    const int lane = tid & 31;
    const int warp = tid >> 5;

    __shared__ float sh_part[8][H_];
    __shared__ float sh_wcol[H_];
    __shared__ float sh_bsum;

    // parallel colsum(W): 1024 threads, col = tid&127, row-group = tid>>7
    {
        const int c = tid & (H_ - 1);
        const int g = tid >> 7;
        const float* wp = W + (g * 16) * H_ + c;
        float a0 = 0.f, a1 = 0.f, a2 = 0.f, a3 = 0.f;
        #pragma unroll
        for (int r = 0; r < 16; r += 4) {
            a0 += wp[(r + 0) * H_];
            a1 += wp[(r + 1) * H_];
            a2 += wp[(r + 2) * H_];
            a3 += wp[(r + 3) * H_];
        }
        sh_part[g][c] = (a0 + a1) + (a2 + a3);
    }
    if (warp == 0) {
        float bs = bias[lane] + bias[lane + 32] + bias[lane + 64] + bias[lane + 96];
        #pragma unroll
        for (int o = 16; o > 0; o >>= 1) bs += __shfl_xor_sync(0xffffffffu, bs, o);
        if (lane == 0) sh_bsum = bs;
    }
    __syncthreads();
    if (tid < H_) {
        float s = 0.f;
        #pragma unroll
        for (int g = 0; g < 8; ++g) s += sh_part[g][tid];
        sh_wcol[tid] = s;
    }
    __syncthreads();

    // one warp per key row: 64 blocks * 32 warps = 2048 rows
    const int row = blockIdx.x * 32 + warp;        // [0, 2048)
    const float4 k4 = reinterpret_cast<const float4*>(keys)[row * (H_ / 4) + lane];
    const float4 w4 = reinterpret_cast<const float4*>(sh_wcol)[lane];
    float acc = k4.x * w4.x + k4.y * w4.y + k4.z * w4.z + k4.w * w4.w;
    #pragma unroll
    for (int o = 16; o > 0; o >>= 1) acc += __shfl_xor_sync(0xffffffffu, acc, o);
    if (lane == 0) g_ks[row] = SCALE_ * (acc + sh_bsum);
}

// ---------------------------------------------------------------------------
// K2: softmax over m per batch. grid 2 x 1024.
// ---------------------------------------------------------------------------
__global__ __launch_bounds__(1024) void k_smax() {
    const int b = blockIdx.x;
    const int tid = threadIdx.x;
    const int lane = tid & 31;
    const int warp = tid >> 5;

    __shared__ float red[32];
    __shared__ float red2[32];

    const float x = g_ks[b * M_ + tid];

    float m = x;
    #pragma unroll
    for (int o = 16; o > 0; o >>= 1) m = fmaxf(m, __shfl_xor_sync(0xffffffffu, m, o));
    if (lane == 0) red[warp] = m;
    __syncthreads();
    if (tid < 32) {
        float v = red[tid];
        #pragma unroll
        for (int o = 16; o > 0; o >>= 1) v = fmaxf(v, __shfl_xor_sync(0xffffffffu, v, o));
        red[tid] = v;
    }
    __syncthreads();
    const float e = __expf(x - red[0]);

    float s = e;
    #pragma unroll
    for (int o = 16; o > 0; o >>= 1) s += __shfl_xor_sync(0xffffffffu, s, o);
    if (lane == 0) red2[warp] = s;
    __syncthreads();
    if (tid < 32) {
        float v = red2[tid];
        #pragma unroll
        for (int o = 16; o > 0; o >>= 1) v += __shfl_xor_sync(0xffffffffu, v, o);
        red2[tid] = v;
    }
    __syncthreads();

    g_s[b * M_ + tid] = e / red2[0];
}

// ---------------------------------------------------------------------------
// K3: out[b,n,m] = s[b,m] * values[b,n]. grid 512 x 256, 4 rows per block.
// ---------------------------------------------------------------------------
__global__ __launch_bounds__(256) void k_out(const float* __restrict__ values,
                                             float* __restrict__ out) {
    const int tid = threadIdx.x;
    const int row0 = blockIdx.x * 4;               // 512 blocks * 4 = 2048 rows
    const int b = row0 >> 10;

    const float4 s = reinterpret_cast<const float4*>(g_s)[(b << 8) + tid];
    float4* o4 = reinterpret_cast<float4*>(out);

    #pragma unroll
    for (int r = 0; r < 4; ++r) {
        const int row = row0 + r;
        const float v = __ldg(values + row);
        o4[(size_t)row * 256 + tid] =
            make_float4(s.x * v, s.y * v, s.z * v, s.w * v);
    }
}

extern "C" void kernel_launch(void* const* d_in, const int* in_sizes, int n_in,
                              void* d_out, int out_size) {
    // metadata order: queries, keys, values, W, b
    const float* keys   = (const float*)d_in[1];
    const float* values = (const float*)d_in[2];
    const float* W      = (const float*)d_in[3];
    const float* bias   = (const float*)d_in[4];
    float* out = (float*)d_out;

    k_ks<<<64, 1024>>>(keys, W, bias);
    k_smax<<<B_, 1024>>>();
    k_out<<<512, 256>>>(values, out);
}

// round 4
// speedup vs baseline: 3.2198x; 1.0650x over previous
#include <cuda_runtime.h>
#include <cuda_bf16.h>

#define B_  2
#define N_  1024
#define M_  1024
#define H_  128
#define G_  128          // grid size (single wave on 148 SMs)
#define SCALE_ (1.0f / 6.964404506368992f)  // 1 / 128^0.4

__device__ float g_ks[B_ * M_];          // scaled logits
__device__ unsigned g_count;             // zero-init; monotonic ticket barrier

__global__ __launch_bounds__(1024) void k_fused(const float* __restrict__ keys,
                                                const float* __restrict__ values,
                                                const float* __restrict__ W,
                                                const float* __restrict__ bias,
                                                float* __restrict__ out) {
    const int tid = threadIdx.x;
    const int lane = tid & 31;
    const int warp = tid >> 5;
    const int blk = blockIdx.x;

    __shared__ float sh_part[8][H_];     // 4 KB, reused later as sh_s
    __shared__ float sh_wcol[H_];
    __shared__ float sh_bsum;
    __shared__ float red[32];
    __shared__ float red2[32];

    // ---------------- Phase 1: wcol = colsum(W), bsum = sum(bias) ----------
    {
        const int c = tid & (H_ - 1);
        const int g = tid >> 7;
        const float* wp = W + (g * 16) * H_ + c;
        float a0 = 0.f, a1 = 0.f, a2 = 0.f, a3 = 0.f;
        #pragma unroll
        for (int r = 0; r < 16; r += 4) {
            a0 += wp[(r + 0) * H_];
            a1 += wp[(r + 1) * H_];
            a2 += wp[(r + 2) * H_];
            a3 += wp[(r + 3) * H_];
        }
        sh_part[g][c] = (a0 + a1) + (a2 + a3);
    }
    if (warp == 0) {
        float bs = bias[lane] + bias[lane + 32] + bias[lane + 64] + bias[lane + 96];
        #pragma unroll
        for (int o = 16; o > 0; o >>= 1) bs += __shfl_xor_sync(0xffffffffu, bs, o);
        if (lane == 0) sh_bsum = bs;
    }
    __syncthreads();
    if (tid < H_) {
        float s = 0.f;
        #pragma unroll
        for (int g = 0; g < 8; ++g) s += sh_part[g][tid];
        sh_wcol[tid] = s;
    }
    __syncthreads();

    // ---------------- Phase 2: 16 key-row dots per block --------------------
    // rows blk*16 .. blk*16+15; warp w < 16 handles one row (float4 per lane).
    if (warp < 16) {
        const int row = blk * 16 + warp;
        const float4 k4 = reinterpret_cast<const float4*>(keys)[row * (H_ / 4) + lane];
        const float4 w4 = reinterpret_cast<const float4*>(sh_wcol)[lane];
        float acc = k4.x * w4.x + k4.y * w4.y + k4.z * w4.z + k4.w * w4.w;
        #pragma unroll
        for (int o = 16; o > 0; o >>= 1) acc += __shfl_xor_sync(0xffffffffu, acc, o);
        if (lane == 0) __stcg(&g_ks[row], SCALE_ * (acc + sh_bsum));
    }

    // ---------------- Grid barrier (monotonic ticket, replay-safe) ----------
    __syncthreads();
    if (tid == 0) {
        __threadfence();
        const unsigned ticket = atomicAdd(&g_count, 1u);
        const unsigned target = (ticket / G_ + 1u) * G_;
        while (*((volatile unsigned*)&g_count) < target) { }
        __threadfence();
    }
    __syncthreads();

    // ---------------- Phase 3: softmax stats (redundant per block) ----------
    const int b = blk >> 6;                       // 64 blocks per batch
    const float x = __ldcg(&g_ks[b * M_ + tid]);

    float m = x;
    #pragma unroll
    for (int o = 16; o > 0; o >>= 1) m = fmaxf(m, __shfl_xor_sync(0xffffffffu, m, o));
    if (lane == 0) red[warp] = m;
    __syncthreads();
    if (tid < 32) {
        float v = red[tid];
        #pragma unroll
        for (int o = 16; o > 0; o >>= 1) v = fmaxf(v, __shfl_xor_sync(0xffffffffu, v, o));
        red[tid] = v;
    }
    __syncthreads();
    const float e = __expf(x - red[0]);

    float s = e;
    #pragma unroll
    for (int o = 16; o > 0; o >>= 1) s += __shfl_xor_sync(0xffffffffu, s, o);
    if (lane == 0) red2[warp] = s;
    __syncthreads();
    if (tid < 32) {
        float v = red2[tid];
        #pragma unroll
        for (int o = 16; o > 0; o >>= 1) v += __shfl_xor_sync(0xffffffffu, v, o);
        red2[tid] = v;
    }
    __syncthreads();

    float* sh_s = &sh_part[0][0];                 // reuse 4 KB smem
    sh_s[tid] = e / red2[0];
    __syncthreads();

    // ---------------- Phase 4: write 16 output rows -------------------------
    // 1024 threads = 4 row-quarters x 256 cols; 4 iterations of 4 rows each.
    const int quarter = tid >> 8;                 // 0..3
    const int col = tid & 255;                    // float4 column
    const float4 s4 = reinterpret_cast<const float4*>(sh_s)[col];
    float4* o4 = reinterpret_cast<float4*>(out);

    #pragma unroll
    for (int i = 0; i < 4; ++i) {
        const int row = blk * 16 + i * 4 + quarter;
        const float v = __ldg(values + row);      // values flat [B*N]
        o4[(size_t)row * 256 + col] =
            make_float4(s4.x * v, s4.y * v, s4.z * v, s4.w * v);
    }
}

extern "C" void kernel_launch(void* const* d_in, const int* in_sizes, int n_in,
                              void* d_out, int out_size) {
    // metadata order: queries, keys, values, W, b
    const float* keys   = (const float*)d_in[1];
    const float* values = (const float*)d_in[2];
    const float* W      = (const float*)d_in[3];
    const float* bias   = (const float*)d_in[4];
    float* out = (float*)d_out;

    k_fused<<<G_, 1024>>>(keys, values, W, bias, out);
}